// round 12
// baseline (speedup 1.0000x reference)
#include <cuda_runtime.h>
#include <cuda_bf16.h>
#include <cstdint>

// ---------------------------------------------------------------------------
// Problem constants
// ---------------------------------------------------------------------------
#define T_STEPS   1024
#define BATCH     64
#define N_IN      256
#define N_HID     512
#define M_TOTAL   (T_STEPS * BATCH)       // 65536
#define YN        (BATCH * N_HID)         // 32768

#define GAIN_REC  0.04419417382415922f    // 1/sqrt(512)
#define DT_H      0.1f

__device__ float g_ext[(size_t)M_TOTAL * N_HID];   // inputs @ W_ih + b_ih

// ---------------------------------------------------------------------------
// Kernel A: ext = inputs @ W_ih + b_ih   (unchanged; ~0.45ms)
// ---------------------------------------------------------------------------
#define TA_M 64
#define TA_N 64
#define TA_K 32

__global__ __launch_bounds__(256) void ext_gemm_kernel(
    const float* __restrict__ A, const float* __restrict__ W,
    const float* __restrict__ bias)
{
    __shared__ float As[TA_K][TA_M + 4];
    __shared__ float Bs[TA_K][TA_N];

    const int tid = threadIdx.x;
    const int tx  = tid & 15;
    const int ty  = tid >> 4;
    const int m0  = blockIdx.y * TA_M;
    const int n0  = blockIdx.x * TA_N;

    float acc[4][4];
#pragma unroll
    for (int i = 0; i < 4; ++i)
#pragma unroll
        for (int j = 0; j < 4; ++j) acc[i][j] = 0.f;

    for (int kt = 0; kt < N_IN; kt += TA_K) {
#pragma unroll
        for (int j = 0; j < 2; ++j) {
            int f  = tid + j * 256;
            int r  = f >> 3;
            int c4 = f & 7;
            float4 v = *(const float4*)&A[(size_t)(m0 + r) * N_IN + kt + c4 * 4];
            As[c4 * 4 + 0][r] = v.x;
            As[c4 * 4 + 1][r] = v.y;
            As[c4 * 4 + 2][r] = v.z;
            As[c4 * 4 + 3][r] = v.w;
        }
#pragma unroll
        for (int j = 0; j < 2; ++j) {
            int f  = tid + j * 256;
            int r  = f >> 4;
            int c4 = f & 15;
            *(float4*)&Bs[r][c4 * 4] =
                *(const float4*)&W[(size_t)(kt + r) * N_HID + n0 + c4 * 4];
        }
        __syncthreads();
#pragma unroll
        for (int k = 0; k < TA_K; ++k) {
            float a[4], bb[4];
            *(float4*)a  = *(const float4*)&As[k][ty * 4];
            *(float4*)bb = *(const float4*)&Bs[k][tx * 4];
#pragma unroll
            for (int i = 0; i < 4; ++i)
#pragma unroll
                for (int j = 0; j < 4; ++j)
                    acc[i][j] = fmaf(a[i], bb[j], acc[i][j]);
        }
        __syncthreads();
    }

    float4 bv = *(const float4*)&bias[n0 + tx * 4];
#pragma unroll
    for (int i = 0; i < 4; ++i) {
        int m = m0 + ty * 4 + i;
        float4 o;
        o.x = acc[i][0] + bv.x;
        o.y = acc[i][1] + bv.y;
        o.z = acc[i][2] + bv.z;
        o.w = acc[i][3] + bv.w;
        *(float4*)&g_ext[(size_t)m * N_HID + n0 + tx * 4] = o;
    }
}

// ---------------------------------------------------------------------------
// Kernel B: persistent recurrence, 16 clusters x 8 CTAs, 768 threads.
//   W_hh slice in SMEM (round-7 proven dot). Cluster's 4 batch rows split
//   into 2 pipelined groups (rows 01 / 23). Dot warps (0-15) alternate
//   g0/g1 within each step; dyn warps split into two independent halves:
//   warps 16-19 serve group 0, warps 20-23 serve group 1.
//   Barrier (1+g): 512 dot threads arrive + 128 dyn-half threads sync
//   => participant count 640 (round-11 bug was declaring 768 here).
// ---------------------------------------------------------------------------
#define RNT 768
#define BAR_MAIN_CNT 640               // 512 dot + 128 dyn (one group half)

// SMEM layout (float indices); gp = g*2 + parity (4 slots)
#define WS_F    0                      // W slice [k4][hl] float4: 32768 floats
#define YS_F    32768                  // [gp][src(8)][r(2)][64] = 4096 floats
#define RED_F   36864                  // [gp][kh(8)][r(2)][64]  = 4096 floats
#define STAG_F  40960                  // [gp][128]              = 512 floats
#define MBAR_F  41472                  // 32 mbarriers (256 B)
#define SMEM_R_BYTES ((MBAR_F + 64) * 4)

#define TX_BYTES 512u                  // per source rank per group: 2x64x4 B

__device__ __forceinline__ void mbar_init(uint32_t a, uint32_t cnt) {
    asm volatile("mbarrier.init.shared.b64 [%0], %1;" :: "r"(a), "r"(cnt) : "memory");
}
__device__ __forceinline__ void mbar_expect_tx(uint32_t a, uint32_t bytes) {
    asm volatile("mbarrier.arrive.expect_tx.shared.b64 _, [%0], %1;"
                 :: "r"(a), "r"(bytes) : "memory");
}
__device__ __forceinline__ void mbar_wait_parity(uint32_t a, uint32_t par) {
    asm volatile("{\n\t.reg .pred P;\n\t"
                 "WL_%=:\n\t"
                 "mbarrier.try_wait.parity.acquire.cluster.shared::cta.b64 P, [%0], %1, 0x989680;\n\t"
                 "@P bra WD_%=;\n\t"
                 "bra WL_%=;\n\t"
                 "WD_%=:\n\t}"
                 :: "r"(a), "r"(par) : "memory");
}
// 512B bulk copy: my smem -> dest rank's smem, tx-completing dest's mbarrier
__device__ __forceinline__ void bulk_s2s(uint32_t dstLocal, uint32_t srcLocal,
                                         uint32_t mbarLocal, uint32_t rank) {
    asm volatile("{\n\t.reg .b32 rd, rm;\n\t"
                 "mapa.shared::cluster.u32 rd, %0, %3;\n\t"
                 "mapa.shared::cluster.u32 rm, %2, %3;\n\t"
                 "cp.async.bulk.shared::cluster.shared::cta.mbarrier::complete_tx::bytes "
                 "[rd], [%1], %4, [rm];\n\t}"
                 :: "r"(dstLocal), "r"(srcLocal), "r"(mbarLocal), "r"(rank),
                    "n"(TX_BYTES)
                 : "memory");
}
__device__ __forceinline__ float tanh_approx(float x) {
    float r;
    asm("tanh.approx.f32 %0, %1;" : "=f"(r) : "f"(x));
    return r;
}
__device__ __forceinline__ void ffma2(unsigned long long& acc,
                                      unsigned long long a,
                                      unsigned long long b) {
    asm("fma.rn.f32x2 %0, %1, %2, %0;" : "+l"(acc) : "l"(a), "l"(b));
}

__global__ void __cluster_dims__(8, 1, 1) __launch_bounds__(RNT, 1)
horn_rec11(const float* __restrict__ W_hh,
           const float* __restrict__ b_hh,
           const float* __restrict__ alpha,
           const float* __restrict__ omega,
           const float* __restrict__ gamma,
           const float* __restrict__ vvec,
           float* __restrict__ out)
{
    extern __shared__ float smem[];

    const int tid  = threadIdx.x;
    const int bg   = blockIdx.x >> 3;           // cluster id (16)
    const int rank = blockIdx.x & 7;            // h0 = rank*64
    const int h0   = rank * 64;
    const int warp = tid >> 5;
    const uint32_t smem_u32 = (uint32_t)__cvta_generic_to_shared(smem);
    const uint32_t mbar_base = smem_u32 + MBAR_F * 4;  // mb[g][kh][p]: (g*16+kh*2+p)*8

    // ---- fill W slice: ws[k4*256 + col*4 + (k&3)] (float4 packs a k-quad) ----
    for (int idx = tid; idx < 64 * N_HID; idx += RNT) {
        int k = idx >> 6;
        int l = idx & 63;
        smem[WS_F + (k >> 2) * 256 + l * 4 + (k & 3)] =
            W_hh[(size_t)k * N_HID + h0 + l];
    }

    if (tid < 32) mbar_init(mbar_base + tid * 8, 1);
    __syncthreads();
    if (tid < 32) mbar_expect_tx(mbar_base + tid * 8, TX_BYTES);
    __syncthreads();
    asm volatile("barrier.cluster.arrive.aligned;" ::: "memory");
    asm volatile("barrier.cluster.wait.aligned;"   ::: "memory");

    if (warp < 16) {
        // =================== DOT WARPS (tid 0..511) ===================
        const int kh = tid >> 6;                // k-slice = source rank 0..7
        const int hl = tid & 63;
        const ulonglong2* wp = ((const ulonglong2*)smem) + (kh * 16) * 64 + hl;

        for (int t = 0; t < T_STEPS; ++t) {
#pragma unroll
            for (int g = 0; g < 2; ++g) {
                if (t > 0) {
                    const int p = (t - 1) & 1;
                    const uint32_t mb = mbar_base + (g * 16 + kh * 2 + p) * 8;
                    mbar_wait_parity(mb, (unsigned)(((t - 1) >> 1) & 1));
                    if ((tid & 63) == 0) mbar_expect_tx(mb, TX_BYTES);

                    // y block from source rank kh, group g: [r(2)][64]
                    const ulonglong2* yb = (const ulonglong2*)
                        (smem + YS_F + (g * 2 + p) * 1024 + kh * 128);
                    unsigned long long a0x = 0ull, a0y = 0ull;
                    unsigned long long a1x = 0ull, a1y = 0ull;
#pragma unroll
                    for (int j = 0; j < 16; ++j) {
                        ulonglong2 wv = wp[j * 64];
                        ulonglong2 y0 = yb[j];
                        ulonglong2 y1 = yb[16 + j];
                        ffma2(a0x, y0.x, wv.x);
                        ffma2(a0y, y0.y, wv.y);
                        ffma2(a1x, y1.x, wv.x);
                        ffma2(a1y, y1.y, wv.y);
                    }
                    float* rp = smem + RED_F + (g * 2 + (t & 1)) * 1024
                              + kh * 128 + hl;
                    float2 f0x = *(float2*)&a0x, f0y = *(float2*)&a0y;
                    float2 f1x = *(float2*)&a1x, f1y = *(float2*)&a1y;
                    rp[0]  = (f0x.x + f0x.y) + (f0y.x + f0y.y);
                    rp[64] = (f1x.x + f1x.y) + (f1y.x + f1y.y);
                }
                {
                    int barid = 1 + g;
                    asm volatile("bar.arrive %0, %1;"
                                 :: "r"(barid), "n"(BAR_MAIN_CNT) : "memory");
                }
            }
        }
        // drain final in-flight phase per group (y_1023 sends, parity 1)
        mbar_wait_parity(mbar_base + (0 * 16 + kh * 2 + 1) * 8, 1u);
        mbar_wait_parity(mbar_base + (1 * 16 + kh * 2 + 1) * 8, 1u);
    } else {
        // ============ DYN WARPS: two independent 128-thread halves ==========
        const int tid2 = tid - 512;             // 0..255
        const int g    = tid2 >> 7;             // my group (fixed)
        const int q    = tid2 & 127;            // index within group
        const int r    = q >> 6;                // local row in group
        const int hl   = q & 63;
        const int dh   = h0 + hl;

        const float bhh  = __ldg(&b_hh[dh]);
        const float dtal = DT_H * __ldg(&alpha[dh]);
        const float om   = __ldg(&omega[dh]);
        const float om2  = om * om;
        const float g2   = 2.f * __ldg(&gamma[dh]);
        const float vv   = __ldg(&vvec[dh]);
        const int b = bg * 4 + g * 2 + r;
        const float* ep = g_ext + (size_t)b * N_HID + dh;
        float*       op = out   + (size_t)b * N_HID + dh;

        float x = 0.f;
        float lin  = 0.f;                       // y + h*(-om2*x - g2*y)
        float base = GAIN_REC * bhh;            // GAIN*(bhh + vv*x)
        float ec = __ldcg((float*)ep);          // ext t
        float e1 = __ldcg((float*)(ep + YN));   // ext t+1

        const int bar_main = 1 + g;             // 640-way with dot warps
        const int bar_half = 3 + g;             // 128-way within my half

        for (int t = 0; t < T_STEPS; ++t) {
            asm volatile("bar.sync %0, %1;"
                         :: "r"(bar_main), "n"(BAR_MAIN_CNT) : "memory");

            float acc = 0.f;
            if (t > 0) {
                const float* rp = smem + RED_F + (g * 2 + (t & 1)) * 1024 + q;
#pragma unroll
                for (int k = 0; k < 8; ++k)
                    acc += rp[k * 128];
            }
            float inp = ec + fmaf(GAIN_REC, acc, base);
            float th  = tanh_approx(inp);
            float yn  = fmaf(dtal, th, lin);
            float xn  = fmaf(DT_H, yn, x);
            smem[STAG_F + (g * 2 + (t & 1)) * 128 + q] = yn;
            op[(size_t)t * YN] = xn;
            lin  = fmaf(DT_H, fmaf(-om2, xn, -g2 * yn), yn);
            base = GAIN_REC * fmaf(vv, xn, bhh);
            x  = xn;
            ec = e1;
            e1 = __ldcg((float*)(ep + (size_t)((t + 2) & (T_STEPS - 1)) * YN));

            asm volatile("bar.sync %0, %1;" :: "r"(bar_half), "n"(128) : "memory");

            // ---- y exchange: 8 elected threads, one 512B bulk copy each ----
            if (q < 8) {
                asm volatile("fence.proxy.async.shared::cta;" ::: "memory");
                const uint32_t src = smem_u32
                    + (uint32_t)((STAG_F + (g * 2 + (t & 1)) * 128) * 4);
                const uint32_t dst = smem_u32
                    + (uint32_t)((YS_F + (g * 2 + (t & 1)) * 1024
                                  + rank * 128) * 4);
                const uint32_t mbl = mbar_base
                    + (g * 16 + rank * 2 + (t & 1)) * 8;
                bulk_s2s(dst, src, mbl, (uint32_t)q);
            }
        }
    }

    asm volatile("barrier.cluster.arrive.aligned;" ::: "memory");
    asm volatile("barrier.cluster.wait.aligned;"   ::: "memory");
}

// ---------------------------------------------------------------------------
// Launch
// ---------------------------------------------------------------------------
extern "C" void kernel_launch(void* const* d_in, const int* in_sizes, int n_in,
                              void* d_out, int out_size)
{
    const float* inputs = (const float*)d_in[0];
    const float* W_ih   = (const float*)d_in[1];
    const float* b_ih   = (const float*)d_in[2];
    const float* W_hh   = (const float*)d_in[3];
    const float* b_hh   = (const float*)d_in[4];
    const float* alpha  = (const float*)d_in[5];
    const float* omega  = (const float*)d_in[6];
    const float* gamma  = (const float*)d_in[7];
    const float* v      = (const float*)d_in[8];
    float* out = (float*)d_out;

    (void)in_sizes; (void)n_in; (void)out_size;

    cudaFuncSetAttribute(horn_rec11,
                         cudaFuncAttributeMaxDynamicSharedMemorySize,
                         SMEM_R_BYTES);

    dim3 gA(N_HID / TA_N, M_TOTAL / TA_M);
    ext_gemm_kernel<<<gA, 256>>>(inputs, W_ih, b_ih);

    horn_rec11<<<128, RNT, SMEM_R_BYTES>>>(W_hh, b_hh, alpha, omega,
                                           gamma, v, out);
}

// round 13
// speedup vs baseline: 1.1247x; 1.1247x over previous
#include <cuda_runtime.h>
#include <cuda_bf16.h>
#include <cstdint>

// ---------------------------------------------------------------------------
// Problem constants
// ---------------------------------------------------------------------------
#define T_STEPS   1024
#define BATCH     64
#define N_IN      256
#define N_HID     512
#define M_TOTAL   (T_STEPS * BATCH)       // 65536
#define YN        (BATCH * N_HID)         // 32768

#define GAIN_REC  0.04419417382415922f    // 1/sqrt(512)
#define DT_H      0.1f

__device__ float g_ext[(size_t)M_TOTAL * N_HID];   // inputs @ W_ih + b_ih

// ---------------------------------------------------------------------------
// Kernel A: ext = inputs @ W_ih + b_ih  (+ register-prefetch pipeline)
// ---------------------------------------------------------------------------
#define TA_M 64
#define TA_N 64
#define TA_K 32

__global__ __launch_bounds__(256) void ext_gemm_kernel(
    const float* __restrict__ A, const float* __restrict__ W,
    const float* __restrict__ bias)
{
    __shared__ float As[TA_K][TA_M + 4];
    __shared__ float Bs[TA_K][TA_N];

    const int tid = threadIdx.x;
    const int tx  = tid & 15;
    const int ty  = tid >> 4;
    const int m0  = blockIdx.y * TA_M;
    const int n0  = blockIdx.x * TA_N;

    // per-thread load coords (2 A chunks, 2 B chunks per tile)
    int aR[2], aC[2], bR[2], bC[2];
#pragma unroll
    for (int j = 0; j < 2; ++j) {
        int f = tid + j * 256;
        aR[j] = f >> 3;  aC[j] = f & 7;
        bR[j] = f >> 4;  bC[j] = f & 15;
    }

    float acc[4][4];
#pragma unroll
    for (int i = 0; i < 4; ++i)
#pragma unroll
        for (int j = 0; j < 4; ++j) acc[i][j] = 0.f;

    // prefetch tile 0 into registers
    float4 ra[2], rb[2];
#pragma unroll
    for (int j = 0; j < 2; ++j) {
        ra[j] = *(const float4*)&A[(size_t)(m0 + aR[j]) * N_IN + aC[j] * 4];
        rb[j] = *(const float4*)&W[(size_t)bR[j] * N_HID + n0 + bC[j] * 4];
    }

    for (int kt = 0; kt < N_IN; kt += TA_K) {
        // commit prefetched regs to smem
#pragma unroll
        for (int j = 0; j < 2; ++j) {
            As[aC[j] * 4 + 0][aR[j]] = ra[j].x;
            As[aC[j] * 4 + 1][aR[j]] = ra[j].y;
            As[aC[j] * 4 + 2][aR[j]] = ra[j].z;
            As[aC[j] * 4 + 3][aR[j]] = ra[j].w;
            *(float4*)&Bs[bR[j]][bC[j] * 4] = rb[j];
        }
        __syncthreads();

        // prefetch next tile while computing this one
        if (kt + TA_K < N_IN) {
#pragma unroll
            for (int j = 0; j < 2; ++j) {
                ra[j] = *(const float4*)&A[(size_t)(m0 + aR[j]) * N_IN
                                           + kt + TA_K + aC[j] * 4];
                rb[j] = *(const float4*)&W[(size_t)(kt + TA_K + bR[j]) * N_HID
                                           + n0 + bC[j] * 4];
            }
        }

#pragma unroll
        for (int k = 0; k < TA_K; ++k) {
            float a[4], bb[4];
            *(float4*)a  = *(const float4*)&As[k][ty * 4];
            *(float4*)bb = *(const float4*)&Bs[k][tx * 4];
#pragma unroll
            for (int i = 0; i < 4; ++i)
#pragma unroll
                for (int j = 0; j < 4; ++j)
                    acc[i][j] = fmaf(a[i], bb[j], acc[i][j]);
        }
        __syncthreads();
    }

    float4 bv = *(const float4*)&bias[n0 + tx * 4];
#pragma unroll
    for (int i = 0; i < 4; ++i) {
        int m = m0 + ty * 4 + i;
        float4 o;
        o.x = acc[i][0] + bv.x;
        o.y = acc[i][1] + bv.y;
        o.z = acc[i][2] + bv.z;
        o.w = acc[i][3] + bv.w;
        *(float4*)&g_ext[(size_t)m * N_HID + n0 + tx * 4] = o;
    }
}

// ---------------------------------------------------------------------------
// Kernel B: persistent recurrence, 16 clusters x 8 CTAs, 768 threads.
//   Round-7 proven design, single group of 4 rows. One change: dyn warps
//   broadcast eagerly — each dyn warp __syncwarp()s after its own 32 yn
//   stores and lanes 0-7 send that warp's 128B chunk to the 8 ranks.
//   (8 warps x 128B per dest still total the 1024B expect_tx per source.)
// ---------------------------------------------------------------------------
#define RNT 768

// SMEM layout (float indices)
#define WS_F    0                      // W slice [k4][hl] float4: 32768 floats
#define YS_F    32768                  // 2 bufs x [src(8)][row(4)][64]: 4096 f
#define RED_F   36864                  // 2 bufs x [kh(8)][row(4)][hl(64)]: 4096
#define STAG_F  40960                  // yn staging [row*64+hl]: 256 floats
#define MBAR_F  41216                  // 16 mbarriers (128 B)
#define SMEM_R_BYTES ((MBAR_F + 32) * 4)

#define TX_BYTES   1024u               // per source CTA per dest (8 x 128B)
#define CHUNK_B    128u                // per dyn-warp chunk

__device__ __forceinline__ void mbar_init(uint32_t a, uint32_t cnt) {
    asm volatile("mbarrier.init.shared.b64 [%0], %1;" :: "r"(a), "r"(cnt) : "memory");
}
__device__ __forceinline__ void mbar_expect_tx(uint32_t a, uint32_t bytes) {
    asm volatile("mbarrier.arrive.expect_tx.shared.b64 _, [%0], %1;"
                 :: "r"(a), "r"(bytes) : "memory");
}
__device__ __forceinline__ void mbar_wait_parity(uint32_t a, uint32_t par) {
    asm volatile("{\n\t.reg .pred P;\n\t"
                 "WL_%=:\n\t"
                 "mbarrier.try_wait.parity.acquire.cluster.shared::cta.b64 P, [%0], %1, 0x989680;\n\t"
                 "@P bra WD_%=;\n\t"
                 "bra WL_%=;\n\t"
                 "WD_%=:\n\t}"
                 :: "r"(a), "r"(par) : "memory");
}
// 128B bulk copy: my smem -> dest rank's smem, tx-completing dest's mbarrier
__device__ __forceinline__ void bulk_s2s_128(uint32_t dstLocal, uint32_t srcLocal,
                                             uint32_t mbarLocal, uint32_t rank) {
    asm volatile("{\n\t.reg .b32 rd, rm;\n\t"
                 "mapa.shared::cluster.u32 rd, %0, %3;\n\t"
                 "mapa.shared::cluster.u32 rm, %2, %3;\n\t"
                 "cp.async.bulk.shared::cluster.shared::cta.mbarrier::complete_tx::bytes "
                 "[rd], [%1], %4, [rm];\n\t}"
                 :: "r"(dstLocal), "r"(srcLocal), "r"(mbarLocal), "r"(rank),
                    "n"(CHUNK_B)
                 : "memory");
}
__device__ __forceinline__ float tanh_approx(float x) {
    float r;
    asm("tanh.approx.f32 %0, %1;" : "=f"(r) : "f"(x));
    return r;
}
__device__ __forceinline__ void ffma2(unsigned long long& acc,
                                      unsigned long long a,
                                      unsigned long long b) {
    asm("fma.rn.f32x2 %0, %1, %2, %0;" : "+l"(acc) : "l"(a), "l"(b));
}

__global__ void __cluster_dims__(8, 1, 1) __launch_bounds__(RNT, 1)
horn_rec13(const float* __restrict__ W_hh,
           const float* __restrict__ b_hh,
           const float* __restrict__ alpha,
           const float* __restrict__ omega,
           const float* __restrict__ gamma,
           const float* __restrict__ vvec,
           float* __restrict__ out)
{
    extern __shared__ float smem[];

    const int tid  = threadIdx.x;
    const int bg   = blockIdx.x >> 3;           // cluster id (16)
    const int rank = blockIdx.x & 7;            // h0 = rank*64
    const int h0   = rank * 64;
    const int warp = tid >> 5;
    const int lane = tid & 31;
    const uint32_t smem_u32 = (uint32_t)__cvta_generic_to_shared(smem);
    const uint32_t mbar_base = smem_u32 + MBAR_F * 4;   // mbar[r][p] stride 8B

    // ---- fill W slice: ws[k4*256 + col*4 + (k&3)] (float4 packs a k-quad) ----
    for (int idx = tid; idx < 64 * N_HID; idx += RNT) {
        int k = idx >> 6;
        int l = idx & 63;
        smem[WS_F + (k >> 2) * 256 + l * 4 + (k & 3)] =
            W_hh[(size_t)k * N_HID + h0 + l];
    }

    if (tid < 16) mbar_init(mbar_base + tid * 8, 1);
    __syncthreads();
    if (tid < 16) mbar_expect_tx(mbar_base + tid * 8, TX_BYTES);
    __syncthreads();
    asm volatile("barrier.cluster.arrive.aligned;" ::: "memory");
    asm volatile("barrier.cluster.wait.aligned;"   ::: "memory");

    if (warp < 16) {
        // =================== DOT WARPS (tid 0..511) ===================
        const int kh = tid >> 6;                // k-slice = source rank 0..7
        const int hl = tid & 63;
        const ulonglong2* wp = ((const ulonglong2*)smem) + (kh * 16) * 64 + hl;
        float* red0 = smem + RED_F + kh * 256 + hl;

        for (int t = 0; t < T_STEPS; ++t) {
            if (t > 0) {
                const int p = (t - 1) & 1;
                const uint32_t mb = mbar_base + (kh * 2 + p) * 8;
                mbar_wait_parity(mb, (unsigned)(((t - 1) >> 1) & 1));
                if ((tid & 63) == 0) mbar_expect_tx(mb, TX_BYTES);

                // y block from source rank kh: [row(4)][64]
                const ulonglong2* yb = ((const ulonglong2*)
                    (smem + YS_F + p * 2048)) + kh * 64;
                unsigned long long a0[4], a1[4];
#pragma unroll
                for (int r = 0; r < 4; ++r) { a0[r] = 0ull; a1[r] = 0ull; }
#pragma unroll
                for (int j = 0; j < 16; ++j) {
                    ulonglong2 wv = wp[j * 64];
#pragma unroll
                    for (int r = 0; r < 4; ++r) {
                        ulonglong2 yv = yb[r * 16 + j];
                        ffma2(a0[r], yv.x, wv.x);
                        ffma2(a1[r], yv.y, wv.y);
                    }
                }
                float* rp = red0 + (t & 1) * 2048;
#pragma unroll
                for (int r = 0; r < 4; ++r) {
                    float2 f0 = *(float2*)&a0[r];
                    float2 f1 = *(float2*)&a1[r];
                    rp[r * 64] = (f0.x + f0.y) + (f1.x + f1.y);
                }
            }
            asm volatile("bar.arrive 0, %0;" :: "n"(RNT) : "memory");
        }
        // drain final in-flight phase (y_1023 into mbar[kh][1], parity 1)
        mbar_wait_parity(mbar_base + (kh * 2 + 1) * 8, 1u);
    } else {
        // =================== DYN/COMM WARPS (tid 512..767) ===================
        const int tid2 = tid - 512;             // 0..255
        const int dwarp = tid2 >> 5;            // dyn warp 0..7 (32 yn each)
        const int hl   = tid2 & 63;
        const int dh   = h0 + hl;

        const float bhh  = __ldg(&b_hh[dh]);
        const float dtal = DT_H * __ldg(&alpha[dh]);
        const float om   = __ldg(&omega[dh]);
        const float om2  = om * om;
        const float g2   = 2.f * __ldg(&gamma[dh]);
        const float vv   = __ldg(&vvec[dh]);
        const int b = bg * 4 + (tid2 >> 6);
        const float* ep = g_ext + (size_t)b * N_HID + dh;
        float*       op = out   + (size_t)b * N_HID + dh;

        float x = 0.f;
        float lin  = 0.f;                       // y + h*(-om2*x - g2*y)
        float base = GAIN_REC * bhh;            // GAIN*(bhh + vv*x)
        float ec = __ldcg((float*)ep);          // ext t
        float e1 = __ldcg((float*)(ep + YN));   // ext t+1

        for (int t = 0; t < T_STEPS; ++t) {
            asm volatile("bar.sync 0, %0;" :: "n"(RNT) : "memory");

            float acc = 0.f;
            if (t > 0) {
                const float* rp = smem + RED_F + (t & 1) * 2048 + tid2;
#pragma unroll
                for (int k = 0; k < 8; ++k)
                    acc += rp[k * 256];
            }
            float inp = ec + fmaf(GAIN_REC, acc, base);
            float th  = tanh_approx(inp);
            float yn  = fmaf(dtal, th, lin);
            float xn  = fmaf(DT_H, yn, x);
            smem[STAG_F + tid2] = yn;
            op[(size_t)t * YN] = xn;
            lin  = fmaf(DT_H, fmaf(-om2, xn, -g2 * yn), yn);
            base = GAIN_REC * fmaf(vv, xn, bhh);
            x  = xn;
            ec = e1;
            e1 = __ldcg((float*)(ep + (size_t)((t + 2) & (T_STEPS - 1)) * YN));

            // ---- eager per-warp broadcast: this warp's 32 yn = 128B ----
            __syncwarp();
            if (lane < 8) {
                asm volatile("fence.proxy.async.shared::cta;" ::: "memory");
                const uint32_t src = smem_u32
                    + (uint32_t)((STAG_F + dwarp * 32) * 4);
                const uint32_t dst = smem_u32
                    + (uint32_t)((YS_F + (t & 1) * 2048
                                  + rank * 256 + dwarp * 32) * 4);
                const uint32_t mbl = mbar_base + (rank * 2 + (t & 1)) * 8;
                bulk_s2s_128(dst, src, mbl, (uint32_t)lane);
            }
        }
    }

    asm volatile("barrier.cluster.arrive.aligned;" ::: "memory");
    asm volatile("barrier.cluster.wait.aligned;"   ::: "memory");
}

// ---------------------------------------------------------------------------
// Launch
// ---------------------------------------------------------------------------
extern "C" void kernel_launch(void* const* d_in, const int* in_sizes, int n_in,
                              void* d_out, int out_size)
{
    const float* inputs = (const float*)d_in[0];
    const float* W_ih   = (const float*)d_in[1];
    const float* b_ih   = (const float*)d_in[2];
    const float* W_hh   = (const float*)d_in[3];
    const float* b_hh   = (const float*)d_in[4];
    const float* alpha  = (const float*)d_in[5];
    const float* omega  = (const float*)d_in[6];
    const float* gamma  = (const float*)d_in[7];
    const float* v      = (const float*)d_in[8];
    float* out = (float*)d_out;

    (void)in_sizes; (void)n_in; (void)out_size;

    cudaFuncSetAttribute(horn_rec13,
                         cudaFuncAttributeMaxDynamicSharedMemorySize,
                         SMEM_R_BYTES);

    dim3 gA(N_HID / TA_N, M_TOTAL / TA_M);
    ext_gemm_kernel<<<gA, 256>>>(inputs, W_ih, b_ih);

    horn_rec13<<<128, RNT, SMEM_R_BYTES>>>(W_hh, b_hh, alpha, omega,
                                           gamma, v, out);
}